// round 2
// baseline (speedup 1.0000x reference)
#include <cuda_runtime.h>
#include <math.h>

// Problem constants
#define Bsz   4096
#define OBS   1024
#define EOUT  512
#define H1D   2048
#define H2D   2048

// Scratch (static device globals; no allocations allowed).
// NOTE: addresses are resolved with cudaGetSymbolAddress in kernel_launch —
// never pass the symbol itself from host code (that yields the host shadow).
__device__ float g_e[Bsz * EOUT];        // tanh(obs@We^T+be)
__device__ float g_dW[OBS * EOUT];       // attn_W[:,:,1] - attn_W[:,:,0]
__device__ float g_db[OBS];              // attn_b[:,1]   - attn_b[:,0]
__device__ float g_h1[Bsz * H1D];
__device__ float g_h2[Bsz * H2D];

// ---------------------------------------------------------------------------
// Fold the 2-class softmax into a sigmoid of the logit difference.
// ---------------------------------------------------------------------------
__global__ void prep_diff_kernel(const float* __restrict__ attn_W,
                                 const float* __restrict__ attn_b,
                                 float* __restrict__ dW,
                                 float* __restrict__ db) {
    int i = blockIdx.x * blockDim.x + threadIdx.x;
    if (i < OBS * EOUT) {
        dW[i] = attn_W[2 * i + 1] - attn_W[2 * i + 0];
    }
    if (i < OBS) {
        db[i] = attn_b[2 * i + 1] - attn_b[2 * i + 0];
    }
}

// ---------------------------------------------------------------------------
// Register-blocked SGEMM: C = act(A @ B^T + bias)
//   A: [M,K] row-major (optionally multiplied elementwise by A2, same shape)
//   B: [N,K] row-major (torch Linear weight layout)
//   C: [M,N] row-major
// Tiles: BM=BN=128, BK=8; 256 threads; each thread computes 8x8.
// All dims are multiples of the tiles -> no bounds checks.
// ACT: 0=tanh, 1=sigmoid, 2=identity
// ---------------------------------------------------------------------------
template <int ACT, bool MUL_A>
__global__ __launch_bounds__(256)
void sgemm_bt_kernel(const float* __restrict__ A,
                     const float* __restrict__ A2,
                     const float* __restrict__ B,
                     const float* __restrict__ bias,
                     float* __restrict__ C,
                     int M, int N, int K) {
    const int BM = 128, BN = 128, BK = 8;
    __shared__ float As[BK][BM];
    __shared__ float Bs[BK][BN];

    const int t  = threadIdx.x;        // 0..255
    const int tx = t % 16;             // col group
    const int ty = t / 16;             // row group
    const int m0 = blockIdx.y * BM;
    const int n0 = blockIdx.x * BN;

    float acc[8][8];
#pragma unroll
    for (int i = 0; i < 8; i++)
#pragma unroll
        for (int j = 0; j < 8; j++) acc[i][j] = 0.0f;

    for (int k0 = 0; k0 < K; k0 += BK) {
#pragma unroll
        for (int l = 0; l < 4; l++) {
            int idx = t + l * 256;
            int r = idx / BK;
            int c = idx % BK;
            float v = A[(size_t)(m0 + r) * K + (k0 + c)];
            if (MUL_A) v *= A2[(size_t)(m0 + r) * K + (k0 + c)];
            As[c][r] = v;
        }
#pragma unroll
        for (int l = 0; l < 4; l++) {
            int idx = t + l * 256;
            int r = idx / BK;
            int c = idx % BK;
            Bs[c][r] = B[(size_t)(n0 + r) * K + (k0 + c)];
        }
        __syncthreads();

#pragma unroll
        for (int kk = 0; kk < BK; kk++) {
            float ra[8], rb[8];
#pragma unroll
            for (int i = 0; i < 8; i++) ra[i] = As[kk][ty * 8 + i];
#pragma unroll
            for (int j = 0; j < 8; j++) rb[j] = Bs[kk][tx * 8 + j];
#pragma unroll
            for (int i = 0; i < 8; i++)
#pragma unroll
                for (int j = 0; j < 8; j++)
                    acc[i][j] = fmaf(ra[i], rb[j], acc[i][j]);
        }
        __syncthreads();
    }

#pragma unroll
    for (int i = 0; i < 8; i++) {
        int m = m0 + ty * 8 + i;
#pragma unroll
        for (int j = 0; j < 8; j++) {
            int n = n0 + tx * 8 + j;
            float v = acc[i][j] + bias[n];
            if (ACT == 0) v = tanhf(v);
            else if (ACT == 1) v = 1.0f / (1.0f + expf(-v));
            C[(size_t)m * N + n] = v;
        }
    }
}

// ---------------------------------------------------------------------------
// GEMV: v[b] = dot(h2[b,:], W3[0,:]) + b3[0]   (one block per row)
// ---------------------------------------------------------------------------
__global__ __launch_bounds__(256)
void gemv_kernel(const float* __restrict__ H,
                 const float* __restrict__ W3,
                 const float* __restrict__ b3,
                 float* __restrict__ out) {
    __shared__ float red[8];
    int b = blockIdx.x;
    const float* row = H + (size_t)b * H2D;
    float s = 0.0f;
    for (int k = threadIdx.x; k < H2D; k += 256)
        s = fmaf(row[k], W3[k], s);
    for (int off = 16; off > 0; off >>= 1)
        s += __shfl_down_sync(0xffffffffu, s, off);
    if ((threadIdx.x & 31) == 0) red[threadIdx.x >> 5] = s;
    __syncthreads();
    if (threadIdx.x == 0) {
        float tot = 0.0f;
#pragma unroll
        for (int w = 0; w < 8; w++) tot += red[w];
        out[b] = tot + b3[0];
    }
}

// ---------------------------------------------------------------------------
// Launch
// ---------------------------------------------------------------------------
extern "C" void kernel_launch(void* const* d_in, const int* in_sizes, int n_in,
                              void* d_out, int out_size) {
    const float* obs    = (const float*)d_in[0];   // [4096,1024]
    const float* We     = (const float*)d_in[1];   // [512,1024]
    const float* be     = (const float*)d_in[2];   // [512]
    const float* attn_W = (const float*)d_in[3];   // [1024,512,2]
    const float* attn_b = (const float*)d_in[4];   // [1024,2]
    const float* W1     = (const float*)d_in[5];   // [2048,1024]
    const float* b1     = (const float*)d_in[6];   // [2048]
    const float* W2     = (const float*)d_in[7];   // [2048,2048]
    const float* b2     = (const float*)d_in[8];   // [2048]
    const float* W3     = (const float*)d_in[9];   // [1,2048]
    const float* b3     = (const float*)d_in[10];  // [1]

    float* out_v    = (float*)d_out;            // [4096]
    float* out_attn = (float*)d_out + Bsz;      // [4096,1024]

    // Resolve TRUE device addresses of scratch (host-side symbol decay gives
    // the host shadow — the R1 bug). Deterministic, capture-safe.
    float *e, *dW, *db, *h1, *h2;
    cudaGetSymbolAddress((void**)&e,  g_e);
    cudaGetSymbolAddress((void**)&dW, g_dW);
    cudaGetSymbolAddress((void**)&db, g_db);
    cudaGetSymbolAddress((void**)&h1, g_h1);
    cudaGetSymbolAddress((void**)&h2, g_h2);

    // 1) fold softmax weights
    prep_diff_kernel<<<(OBS * EOUT + 255) / 256, 256>>>(attn_W, attn_b, dW, db);

    // 2) e = tanh(obs @ We^T + be)   [4096,512]
    {
        dim3 grid(EOUT / 128, Bsz / 128);
        sgemm_bt_kernel<0, false><<<grid, 256>>>(obs, nullptr, We, be, e,
                                                 Bsz, EOUT, OBS);
    }
    // 3) attention = sigmoid(e @ diffW^T + diffb)   [4096,1024]
    {
        dim3 grid(OBS / 128, Bsz / 128);
        sgemm_bt_kernel<1, false><<<grid, 256>>>(e, nullptr, dW, db,
                                                 out_attn, Bsz, OBS, EOUT);
    }
    // 4) h1 = tanh((obs*attn) @ W1^T + b1)   [4096,2048]
    {
        dim3 grid(H1D / 128, Bsz / 128);
        sgemm_bt_kernel<0, true><<<grid, 256>>>(obs, out_attn, W1, b1, h1,
                                                Bsz, H1D, OBS);
    }
    // 5) h2 = tanh(h1 @ W2^T + b2)   [4096,2048]
    {
        dim3 grid(H2D / 128, Bsz / 128);
        sgemm_bt_kernel<0, false><<<grid, 256>>>(h1, nullptr, W2, b2, h2,
                                                 Bsz, H2D, H1D);
    }
    // 6) v = h2 @ W3^T + b3   [4096]
    gemv_kernel<<<Bsz, 256>>>(h2, W3, b3, out_v);
}

// round 4
// speedup vs baseline: 4.0645x; 4.0645x over previous
#include <cuda_runtime.h>
#include <math.h>
#include <stdint.h>

// Problem constants
#define Bsz   4096
#define OBS   1024
#define EOUT  512
#define H1D   2048
#define H2D   2048

// Scratch (static device globals; resolved via cudaGetSymbolAddress)
__device__ float g_e[Bsz * EOUT];
__device__ float g_dW[OBS * EOUT];
__device__ float g_db[OBS];
__device__ float g_sa[Bsz * OBS];     // obs * attention
__device__ float g_h1[Bsz * H1D];
__device__ float g_h2[Bsz * H2D];

__device__ __forceinline__ uint32_t cvt_tf32(float x) {
    uint32_t r;
    asm("cvt.rna.tf32.f32 %0, %1;" : "=r"(r) : "f"(x));
    return r;
}

// ---------------------------------------------------------------------------
// prep: fold 2-class softmax into sigmoid(logit diff)
// ---------------------------------------------------------------------------
__global__ void prep_diff_kernel(const float* __restrict__ attn_W,
                                 const float* __restrict__ attn_b,
                                 float* __restrict__ dW, float* __restrict__ db) {
    int i = blockIdx.x * blockDim.x + threadIdx.x;
    if (i < OBS * EOUT) dW[i] = attn_W[2 * i + 1] - attn_W[2 * i];
    if (i < OBS)        db[i] = attn_b[2 * i + 1] - attn_b[2 * i];
}

// ---------------------------------------------------------------------------
// tf32 mma.sync GEMM: C = act(A @ B^T + bias)
//   A:[M,K] fp32 row-major, B:[N,K] fp32 row-major (torch Linear weight)
//   Tile 128x128, BK=32. 256 threads = 8 warps (2 on M x 4 on N), each warp
//   64x32 via 4x4 m16n8k8 tf32 MMAs. Smem padded stride 36: conflict-free
//   fragment reads. All dims are multiples of 128/32 -> no bounds checks.
// ACT: 0 = tanh, 1 = sigmoid (fused second output C2 = obsp * sigmoid)
// ---------------------------------------------------------------------------
template <int ACT>
__global__ __launch_bounds__(256, 2)
void mm_tf32(const float* __restrict__ A, const float* __restrict__ B,
             const float* __restrict__ bias,
             float* __restrict__ C, float* __restrict__ C2,
             const float* __restrict__ obsp,
             int M, int N, int K) {
    __shared__ uint32_t As[128 * 36];
    __shared__ uint32_t Bs[128 * 36];

    const int t    = threadIdx.x;
    const int lane = t & 31;
    const int wid  = t >> 5;
    const int wm   = wid & 1;          // 0..1  (64 rows each)
    const int wn   = wid >> 1;         // 0..3  (32 cols each)
    const int m0   = blockIdx.y * 128;
    const int n0   = blockIdx.x * 128;
    const int qr   = lane >> 2;        // 0..7
    const int qc   = lane & 3;         // 0..3

    float acc[4][4][4];
#pragma unroll
    for (int i = 0; i < 4; ++i)
#pragma unroll
        for (int j = 0; j < 4; ++j)
#pragma unroll
            for (int r = 0; r < 4; ++r) acc[i][j][r] = 0.0f;

    const int gr = t >> 3;             // 0..31: global-load row group
    const int gq = t & 7;              // 0..7 : float4 index within row

    for (int k0 = 0; k0 < K; k0 += 32) {
        // --- global -> smem (cvt to tf32 bits) ---
#pragma unroll
        for (int i = 0; i < 4; ++i) {
            int r = gr + (i << 5);
            float4 v = *(const float4*)(A + (size_t)(m0 + r) * K + k0 + (gq << 2));
            uint32_t* d = As + r * 36 + (gq << 2);
            d[0] = cvt_tf32(v.x); d[1] = cvt_tf32(v.y);
            d[2] = cvt_tf32(v.z); d[3] = cvt_tf32(v.w);
        }
#pragma unroll
        for (int i = 0; i < 4; ++i) {
            int r = gr + (i << 5);
            float4 v = *(const float4*)(B + (size_t)(n0 + r) * K + k0 + (gq << 2));
            uint32_t* d = Bs + r * 36 + (gq << 2);
            d[0] = cvt_tf32(v.x); d[1] = cvt_tf32(v.y);
            d[2] = cvt_tf32(v.z); d[3] = cvt_tf32(v.w);
        }
        __syncthreads();

        // --- compute: 4 k-steps of 8 ---
#pragma unroll
        for (int ks = 0; ks < 4; ++ks) {
            const int kb = ks << 3;
            uint32_t bf[4][2];
#pragma unroll
            for (int nt = 0; nt < 4; ++nt) {
                int nb = wn * 32 + nt * 8 + qr;
                bf[nt][0] = Bs[nb * 36 + kb + qc];
                bf[nt][1] = Bs[nb * 36 + kb + qc + 4];
            }
#pragma unroll
            for (int mt = 0; mt < 4; ++mt) {
                int rb = wm * 64 + mt * 16 + qr;
                uint32_t a0 = As[rb * 36 + kb + qc];
                uint32_t a1 = As[(rb + 8) * 36 + kb + qc];
                uint32_t a2 = As[rb * 36 + kb + qc + 4];
                uint32_t a3 = As[(rb + 8) * 36 + kb + qc + 4];
#pragma unroll
                for (int nt = 0; nt < 4; ++nt) {
                    asm volatile(
                        "mma.sync.aligned.m16n8k8.row.col.f32.tf32.tf32.f32 "
                        "{%0,%1,%2,%3}, {%4,%5,%6,%7}, {%8,%9}, {%0,%1,%2,%3};"
                        : "+f"(acc[mt][nt][0]), "+f"(acc[mt][nt][1]),
                          "+f"(acc[mt][nt][2]), "+f"(acc[mt][nt][3])
                        : "r"(a0), "r"(a1), "r"(a2), "r"(a3),
                          "r"(bf[nt][0]), "r"(bf[nt][1]));
                }
            }
        }
        __syncthreads();
    }

    // --- epilogue: bias + activation (+ fused obs*att), float2 stores ---
#pragma unroll
    for (int mt = 0; mt < 4; ++mt) {
        const int m = m0 + wm * 64 + mt * 16 + qr;
#pragma unroll
        for (int nt = 0; nt < 4; ++nt) {
            const int n = n0 + wn * 32 + nt * 8 + 2 * qc;
            const float bx = bias[n], by = bias[n + 1];
#pragma unroll
            for (int h = 0; h < 2; ++h) {          // row halves: m, m+8
                const int mm = m + 8 * h;
                float vx = acc[mt][nt][2 * h + 0] + bx;
                float vy = acc[mt][nt][2 * h + 1] + by;
                if (ACT == 0) {
                    vx = tanhf(vx); vy = tanhf(vy);
                } else {
                    vx = 1.0f / (1.0f + expf(-vx));
                    vy = 1.0f / (1.0f + expf(-vy));
                }
                float2 o = make_float2(vx, vy);
                *(float2*)(C + (size_t)mm * N + n) = o;
                if (ACT == 1) {
                    float2 ob = *(const float2*)(obsp + (size_t)mm * N + n);
                    float2 s  = make_float2(ob.x * vx, ob.y * vy);
                    *(float2*)(C2 + (size_t)mm * N + n) = s;
                }
            }
        }
    }
}

// ---------------------------------------------------------------------------
// GEMV: v[b] = dot(h2[b,:], W3) + b3
// ---------------------------------------------------------------------------
__global__ __launch_bounds__(256)
void gemv_kernel(const float* __restrict__ H, const float* __restrict__ W3,
                 const float* __restrict__ b3, float* __restrict__ out) {
    __shared__ float red[8];
    int b = blockIdx.x;
    const float* row = H + (size_t)b * H2D;
    float s = 0.0f;
    for (int k = threadIdx.x; k < H2D; k += 256)
        s = fmaf(row[k], W3[k], s);
    for (int off = 16; off > 0; off >>= 1)
        s += __shfl_down_sync(0xffffffffu, s, off);
    if ((threadIdx.x & 31) == 0) red[threadIdx.x >> 5] = s;
    __syncthreads();
    if (threadIdx.x == 0) {
        float tot = 0.0f;
#pragma unroll
        for (int w = 0; w < 8; w++) tot += red[w];
        out[b] = tot + b3[0];
    }
}

// ---------------------------------------------------------------------------
// Launch
// ---------------------------------------------------------------------------
extern "C" void kernel_launch(void* const* d_in, const int* in_sizes, int n_in,
                              void* d_out, int out_size) {
    const float* obs    = (const float*)d_in[0];
    const float* We     = (const float*)d_in[1];
    const float* be     = (const float*)d_in[2];
    const float* attn_W = (const float*)d_in[3];
    const float* attn_b = (const float*)d_in[4];
    const float* W1     = (const float*)d_in[5];
    const float* b1     = (const float*)d_in[6];
    const float* W2     = (const float*)d_in[7];
    const float* b2     = (const float*)d_in[8];
    const float* W3     = (const float*)d_in[9];
    const float* b3     = (const float*)d_in[10];

    float* out_v    = (float*)d_out;
    float* out_attn = (float*)d_out + Bsz;

    float *e, *dW, *db, *sa, *h1, *h2;
    cudaGetSymbolAddress((void**)&e,  g_e);
    cudaGetSymbolAddress((void**)&dW, g_dW);
    cudaGetSymbolAddress((void**)&db, g_db);
    cudaGetSymbolAddress((void**)&sa, g_sa);
    cudaGetSymbolAddress((void**)&h1, g_h1);
    cudaGetSymbolAddress((void**)&h2, g_h2);

    // 1) fold softmax weights
    prep_diff_kernel<<<(OBS * EOUT + 255) / 256, 256>>>(attn_W, attn_b, dW, db);

    // 2) e = tanh(obs @ We^T + be)                 [4096,512]  K=1024
    mm_tf32<0><<<dim3(EOUT / 128, Bsz / 128), 256>>>(
        obs, We, be, e, nullptr, nullptr, Bsz, EOUT, OBS);

    // 3) att = sigmoid(e @ dW^T + db); sa = obs*att  [4096,1024] K=512
    mm_tf32<1><<<dim3(OBS / 128, Bsz / 128), 256>>>(
        e, dW, db, out_attn, sa, obs, Bsz, OBS, EOUT);

    // 4) h1 = tanh(sa @ W1^T + b1)                 [4096,2048] K=1024
    mm_tf32<0><<<dim3(H1D / 128, Bsz / 128), 256>>>(
        sa, W1, b1, h1, nullptr, nullptr, Bsz, H1D, OBS);

    // 5) h2 = tanh(h1 @ W2^T + b2)                 [4096,2048] K=2048
    mm_tf32<0><<<dim3(H2D / 128, Bsz / 128), 256>>>(
        h1, W2, b2, h2, nullptr, nullptr, Bsz, H2D, H1D);

    // 6) v = h2 @ W3^T + b3                        [4096]
    gemv_kernel<<<Bsz, 256>>>(h2, W3, b3, out_v);
}

// round 5
// speedup vs baseline: 4.8722x; 1.1987x over previous
#include <cuda_runtime.h>
#include <math.h>
#include <stdint.h>

#define Bsz   4096
#define OBS   1024
#define EOUT  512
#define H1D   2048
#define H2D   2048

// tf32 scratch (uint32 bit patterns; valid fp32 with low mantissa zeroed)
__device__ uint32_t t_obs[Bsz * OBS];
__device__ uint32_t t_We [EOUT * OBS];
__device__ uint32_t t_dW [OBS * EOUT];
__device__ uint32_t t_W1 [H1D * OBS];
__device__ uint32_t t_W2 [H2D * H1D];
__device__ uint32_t t_e  [Bsz * EOUT];
__device__ uint32_t t_sa [Bsz * OBS];
__device__ uint32_t t_h1 [Bsz * H1D];
__device__ uint32_t t_h2 [Bsz * H2D];
__device__ float    g_db [OBS];

__device__ __forceinline__ uint32_t cvt_tf32(float x) {
    uint32_t r;
    asm("cvt.rna.tf32.f32 %0, %1;" : "=r"(r) : "f"(x));
    return r;
}
__device__ __forceinline__ uint32_t smem_u32(const void* p) {
    uint32_t a;
    asm("{ .reg .u64 t; cvta.to.shared.u64 t, %1; cvt.u32.u64 %0, t; }"
        : "=r"(a) : "l"(p));
    return a;
}

// ---------------------------------------------------------------------------
// prep: convert obs/We/W1/W2 to tf32; fold softmax -> sigmoid diff (tf32 dW)
// ---------------------------------------------------------------------------
__global__ void prep_all(const float* __restrict__ obs, const float* __restrict__ We,
                         const float* __restrict__ W1,  const float* __restrict__ W2,
                         const float* __restrict__ attn_W, const float* __restrict__ attn_b,
                         float* __restrict__ db) {
    const int Q0 = (Bsz * OBS) / 4, Q1 = (EOUT * OBS) / 4, Q2 = (H1D * OBS) / 4,
              Q3 = (H2D * H1D) / 4, Q4 = (OBS * EOUT) / 4;
    const int total = Q0 + Q1 + Q2 + Q3 + Q4;
    int tid0 = blockIdx.x * blockDim.x + threadIdx.x;
    for (int i = tid0; i < total; i += gridDim.x * blockDim.x) {
        int j = i;
        if (j < Q0) {
            float4 v = ((const float4*)obs)[j];
            uint32_t* d = t_obs + 4 * j;
            d[0]=cvt_tf32(v.x); d[1]=cvt_tf32(v.y); d[2]=cvt_tf32(v.z); d[3]=cvt_tf32(v.w);
        } else if ((j -= Q0) < Q1) {
            float4 v = ((const float4*)We)[j];
            uint32_t* d = t_We + 4 * j;
            d[0]=cvt_tf32(v.x); d[1]=cvt_tf32(v.y); d[2]=cvt_tf32(v.z); d[3]=cvt_tf32(v.w);
        } else if ((j -= Q1) < Q2) {
            float4 v = ((const float4*)W1)[j];
            uint32_t* d = t_W1 + 4 * j;
            d[0]=cvt_tf32(v.x); d[1]=cvt_tf32(v.y); d[2]=cvt_tf32(v.z); d[3]=cvt_tf32(v.w);
        } else if ((j -= Q2) < Q3) {
            float4 v = ((const float4*)W2)[j];
            uint32_t* d = t_W2 + 4 * j;
            d[0]=cvt_tf32(v.x); d[1]=cvt_tf32(v.y); d[2]=cvt_tf32(v.z); d[3]=cvt_tf32(v.w);
        } else {
            j -= Q3;   // dW quad j: elements 4j..4j+3 -> attn_W[8j..8j+7]
            float4 p = ((const float4*)attn_W)[2 * j];
            float4 q = ((const float4*)attn_W)[2 * j + 1];
            uint32_t* d = t_dW + 4 * j;
            d[0]=cvt_tf32(p.y - p.x); d[1]=cvt_tf32(p.w - p.z);
            d[2]=cvt_tf32(q.y - q.x); d[3]=cvt_tf32(q.w - q.z);
        }
    }
    if (tid0 < OBS) db[tid0] = attn_b[2 * tid0 + 1] - attn_b[2 * tid0];
}

// ---------------------------------------------------------------------------
// tf32 mma.sync GEMM, cp.async 3-stage pipeline.
//   A:[M,K], B:[N,K] pre-converted tf32 (uint32). C = act(A@B^T + bias).
//   Tile 128x128, BK=32, 256 thr (2x4 warps, 64x32 each), XOR-swizzled smem
//   (no padding): stage = A 16KB + B 16KB; 3 stages = 96KB dynamic.
// ACT 0: tanh, output tf32 (uint32). ACT 1: sigmoid -> C fp32 (attention),
//        C2 = cvt_tf32(obsp * sigmoid) (state_attention, tf32).
// ---------------------------------------------------------------------------
template <int ACT>
__global__ __launch_bounds__(256, 2)
void mm_tf32p(const uint32_t* __restrict__ A, const uint32_t* __restrict__ B,
              const float* __restrict__ bias,
              void* __restrict__ Cv, uint32_t* __restrict__ C2,
              const float* __restrict__ obsp,
              int M, int N, int K) {
    extern __shared__ uint32_t sm[];   // 3 * 8192 words
    const int t    = threadIdx.x;
    const int lane = t & 31;
    const int wid  = t >> 5;
    const int wm   = wid & 1;
    const int wn   = wid >> 1;
    const int m0   = blockIdx.y * 128;
    const int n0   = blockIdx.x * 128;
    const int qr   = lane >> 2;
    const int qc   = lane & 3;

    // load mapping: thread covers rows r+32i, 16B chunk q
    const int r = t >> 3;
    const int q = t & 7;
    const uint32_t smB = smem_u32(sm);

    const uint32_t* aSrc[4];
    const uint32_t* bSrc[4];
    uint32_t aDst[4], bDst[4];          // stage-0 word offsets
#pragma unroll
    for (int i = 0; i < 4; ++i) {
        int rr = r + (i << 5);
        aSrc[i] = A + (size_t)(m0 + rr) * K + (q << 2);
        bSrc[i] = B + (size_t)(n0 + rr) * K + (q << 2);
        uint32_t sw = (uint32_t)((q ^ (rr & 7)) << 2);
        aDst[i] = rr * 32 + sw;
        bDst[i] = 4096 + rr * 32 + sw;
    }

    const int NC = K >> 5;

#define ISSUE_CHUNK(c)                                                        \
    do {                                                                      \
        uint32_t so = (uint32_t)((c) % 3) * 8192u;                            \
        _Pragma("unroll")                                                     \
        for (int i = 0; i < 4; ++i) {                                         \
            uint32_t da = smB + ((so + aDst[i]) << 2);                        \
            asm volatile("cp.async.cg.shared.global [%0], [%1], 16;"          \
                         :: "r"(da), "l"(aSrc[i] + (c) * 32) : "memory");     \
        }                                                                     \
        _Pragma("unroll")                                                     \
        for (int i = 0; i < 4; ++i) {                                         \
            uint32_t dbp = smB + ((so + bDst[i]) << 2);                       \
            asm volatile("cp.async.cg.shared.global [%0], [%1], 16;"          \
                         :: "r"(dbp), "l"(bSrc[i] + (c) * 32) : "memory");    \
        }                                                                     \
        asm volatile("cp.async.commit_group;" ::: "memory");                  \
    } while (0)

    float acc[4][4][4];
#pragma unroll
    for (int i = 0; i < 4; ++i)
#pragma unroll
        for (int j = 0; j < 4; ++j)
#pragma unroll
            for (int k = 0; k < 4; ++k) acc[i][j][k] = 0.0f;

    ISSUE_CHUNK(0);
    ISSUE_CHUNK(1);

    for (int c = 0; c < NC; ++c) {
        if (c + 1 < NC)
            asm volatile("cp.async.wait_group 1;" ::: "memory");
        else
            asm volatile("cp.async.wait_group 0;" ::: "memory");
        __syncthreads();
        if (c + 2 < NC) ISSUE_CHUNK(c + 2);

        const uint32_t bA = (uint32_t)(c % 3) * 8192u;
        const uint32_t bB = bA + 4096u;
#pragma unroll
        for (int ks = 0; ks < 4; ++ks) {
            const int c2 = ks << 1;
            const int ch = c2 ^ qr;            // (row&7)==qr for all frag rows
            uint32_t bf[4][2];
#pragma unroll
            for (int nt = 0; nt < 4; ++nt) {
                uint32_t base = bB + (uint32_t)(wn * 32 + nt * 8 + qr) * 32 + qc;
                bf[nt][0] = sm[base + (ch << 2)];
                bf[nt][1] = sm[base + ((ch ^ 1) << 2)];
            }
#pragma unroll
            for (int mt = 0; mt < 4; ++mt) {
                const int rb = wm * 64 + mt * 16 + qr;
                uint32_t ba0 = bA + (uint32_t)rb * 32 + qc;
                uint32_t ba1 = bA + (uint32_t)(rb + 8) * 32 + qc;
                uint32_t a0 = sm[ba0 + (ch << 2)];
                uint32_t a1 = sm[ba1 + (ch << 2)];
                uint32_t a2 = sm[ba0 + ((ch ^ 1) << 2)];
                uint32_t a3 = sm[ba1 + ((ch ^ 1) << 2)];
#pragma unroll
                for (int nt = 0; nt < 4; ++nt) {
                    asm volatile(
                        "mma.sync.aligned.m16n8k8.row.col.f32.tf32.tf32.f32 "
                        "{%0,%1,%2,%3}, {%4,%5,%6,%7}, {%8,%9}, {%0,%1,%2,%3};"
                        : "+f"(acc[mt][nt][0]), "+f"(acc[mt][nt][1]),
                          "+f"(acc[mt][nt][2]), "+f"(acc[mt][nt][3])
                        : "r"(a0), "r"(a1), "r"(a2), "r"(a3),
                          "r"(bf[nt][0]), "r"(bf[nt][1]));
                }
            }
        }
    }
#undef ISSUE_CHUNK

    // epilogue
#pragma unroll
    for (int mt = 0; mt < 4; ++mt) {
        const int m = m0 + wm * 64 + mt * 16 + qr;
#pragma unroll
        for (int nt = 0; nt < 4; ++nt) {
            const int n = n0 + wn * 32 + nt * 8 + 2 * qc;
            const float bx = bias[n], by = bias[n + 1];
#pragma unroll
            for (int h = 0; h < 2; ++h) {
                const int mm = m + 8 * h;
                float vx = acc[mt][nt][2 * h + 0] + bx;
                float vy = acc[mt][nt][2 * h + 1] + by;
                if (ACT == 0) {
                    vx = tanhf(vx); vy = tanhf(vy);
                    uint2 o = make_uint2(cvt_tf32(vx), cvt_tf32(vy));
                    *(uint2*)((uint32_t*)Cv + (size_t)mm * N + n) = o;
                } else {
                    vx = 1.0f / (1.0f + expf(-vx));
                    vy = 1.0f / (1.0f + expf(-vy));
                    *(float2*)((float*)Cv + (size_t)mm * N + n) = make_float2(vx, vy);
                    float2 ob = *(const float2*)(obsp + (size_t)mm * N + n);
                    uint2 s = make_uint2(cvt_tf32(ob.x * vx), cvt_tf32(ob.y * vy));
                    *(uint2*)(C2 + (size_t)mm * N + n) = s;
                }
            }
        }
    }
}

// ---------------------------------------------------------------------------
// GEMV: v[b] = dot(h2[b,:], W3) + b3   (h2 stored as tf32 bits = valid fp32)
// ---------------------------------------------------------------------------
__global__ __launch_bounds__(256)
void gemv_kernel(const float* __restrict__ H, const float* __restrict__ W3,
                 const float* __restrict__ b3, float* __restrict__ out) {
    __shared__ float red[8];
    int b = blockIdx.x;
    const float* row = H + (size_t)b * H2D;
    float s = 0.0f;
    for (int k = threadIdx.x; k < H2D; k += 256)
        s = fmaf(row[k], W3[k], s);
    for (int off = 16; off > 0; off >>= 1)
        s += __shfl_down_sync(0xffffffffu, s, off);
    if ((threadIdx.x & 31) == 0) red[threadIdx.x >> 5] = s;
    __syncthreads();
    if (threadIdx.x == 0) {
        float tot = 0.0f;
#pragma unroll
        for (int w = 0; w < 8; w++) tot += red[w];
        out[b] = tot + b3[0];
    }
}

// ---------------------------------------------------------------------------
// Launch
// ---------------------------------------------------------------------------
extern "C" void kernel_launch(void* const* d_in, const int* in_sizes, int n_in,
                              void* d_out, int out_size) {
    const float* obs    = (const float*)d_in[0];
    const float* We     = (const float*)d_in[1];
    const float* be     = (const float*)d_in[2];
    const float* attn_W = (const float*)d_in[3];
    const float* attn_b = (const float*)d_in[4];
    const float* W1     = (const float*)d_in[5];
    const float* b1     = (const float*)d_in[6];
    const float* W2     = (const float*)d_in[7];
    const float* b2     = (const float*)d_in[8];
    const float* W3     = (const float*)d_in[9];
    const float* b3     = (const float*)d_in[10];

    float* out_v    = (float*)d_out;
    float* out_attn = (float*)d_out + Bsz;

    uint32_t *pobs, *pWe, *pdW, *pW1, *pW2, *pe, *psa, *ph1, *ph2;
    float* pdb;
    cudaGetSymbolAddress((void**)&pobs, t_obs);
    cudaGetSymbolAddress((void**)&pWe,  t_We);
    cudaGetSymbolAddress((void**)&pdW,  t_dW);
    cudaGetSymbolAddress((void**)&pW1,  t_W1);
    cudaGetSymbolAddress((void**)&pW2,  t_W2);
    cudaGetSymbolAddress((void**)&pe,   t_e);
    cudaGetSymbolAddress((void**)&psa,  t_sa);
    cudaGetSymbolAddress((void**)&ph1,  t_h1);
    cudaGetSymbolAddress((void**)&ph2,  t_h2);
    cudaGetSymbolAddress((void**)&pdb,  g_db);

    const int SMEM = 3 * 8192 * 4;   // 96 KB
    cudaFuncSetAttribute(mm_tf32p<0>, cudaFuncAttributeMaxDynamicSharedMemorySize, SMEM);
    cudaFuncSetAttribute(mm_tf32p<1>, cudaFuncAttributeMaxDynamicSharedMemorySize, SMEM);

    // 1) convert weights/inputs to tf32; fold softmax
    prep_all<<<2048, 256>>>(obs, We, W1, W2, attn_W, attn_b, pdb);

    // 2) e = tanh(obs @ We^T + be)  -> tf32        [4096,512]  K=1024
    mm_tf32p<0><<<dim3(EOUT / 128, Bsz / 128), 256, SMEM>>>(
        pobs, pWe, be, pe, nullptr, nullptr, Bsz, EOUT, OBS);

    // 3) att = sigmoid(e @ dW^T + db) -> fp32 out; sa = tf32(obs*att)
    mm_tf32p<1><<<dim3(OBS / 128, Bsz / 128), 256, SMEM>>>(
        pe, pdW, pdb, out_attn, psa, obs, Bsz, OBS, EOUT);

    // 4) h1 = tanh(sa @ W1^T + b1) -> tf32         [4096,2048] K=1024
    mm_tf32p<0><<<dim3(H1D / 128, Bsz / 128), 256, SMEM>>>(
        psa, pW1, b1, ph1, nullptr, nullptr, Bsz, H1D, OBS);

    // 5) h2 = tanh(h1 @ W2^T + b2) -> tf32         [4096,2048] K=2048
    mm_tf32p<0><<<dim3(H2D / 128, Bsz / 128), 256, SMEM>>>(
        ph1, pW2, b2, ph2, nullptr, nullptr, Bsz, H2D, H1D);

    // 6) v = h2 @ W3^T + b3                        [4096]
    gemv_kernel<<<Bsz, 256>>>((const float*)ph2, W3, b3, out_v);
}

// round 6
// speedup vs baseline: 5.2061x; 1.0685x over previous
#include <cuda_runtime.h>
#include <math.h>
#include <stdint.h>

#define Bsz   4096
#define OBS   1024
#define EOUT  512
#define H1D   2048
#define H2D   2048

// tf32 scratch (uint32 bit patterns; valid fp32 with low mantissa zeroed)
__device__ uint32_t t_obs[Bsz * OBS];
__device__ uint32_t t_We [EOUT * OBS];
__device__ uint32_t t_dW [OBS * EOUT];
__device__ uint32_t t_W1 [H1D * OBS];
__device__ uint32_t t_W2 [H2D * H1D];
__device__ uint32_t t_e  [Bsz * EOUT];
__device__ uint32_t t_sa [Bsz * OBS];
__device__ uint32_t t_h1 [Bsz * H1D];
__device__ uint32_t t_h2 [Bsz * H2D];
__device__ float    g_db [OBS];

__device__ __forceinline__ uint32_t cvt_tf32(float x) {
    uint32_t r;
    asm("cvt.rna.tf32.f32 %0, %1;" : "=r"(r) : "f"(x));
    return r;
}
__device__ __forceinline__ float tanh_ap(float x) {
    float y;
    asm("tanh.approx.f32 %0, %1;" : "=f"(y) : "f"(x));
    return y;
}
__device__ __forceinline__ float sigmoid_ap(float x) {
    return 0.5f + 0.5f * tanh_ap(0.5f * x);
}
__device__ __forceinline__ uint32_t smem_u32(const void* p) {
    uint32_t a;
    asm("{ .reg .u64 t; cvta.to.shared.u64 t, %1; cvt.u32.u64 %0, t; }"
        : "=r"(a) : "l"(p));
    return a;
}

// ---------------------------------------------------------------------------
// prep: convert obs/We/W1/W2 to tf32; fold softmax -> sigmoid diff (tf32 dW)
// ---------------------------------------------------------------------------
__global__ void prep_all(const float* __restrict__ obs, const float* __restrict__ We,
                         const float* __restrict__ W1,  const float* __restrict__ W2,
                         const float* __restrict__ attn_W, const float* __restrict__ attn_b,
                         float* __restrict__ db) {
    const int Q0 = (Bsz * OBS) / 4, Q1 = (EOUT * OBS) / 4, Q2 = (H1D * OBS) / 4,
              Q3 = (H2D * H1D) / 4, Q4 = (OBS * EOUT) / 4;
    const int total = Q0 + Q1 + Q2 + Q3 + Q4;
    int tid0 = blockIdx.x * blockDim.x + threadIdx.x;
    for (int i = tid0; i < total; i += gridDim.x * blockDim.x) {
        int j = i;
        if (j < Q0) {
            float4 v = ((const float4*)obs)[j];
            uint32_t* d = t_obs + 4 * j;
            d[0]=cvt_tf32(v.x); d[1]=cvt_tf32(v.y); d[2]=cvt_tf32(v.z); d[3]=cvt_tf32(v.w);
        } else if ((j -= Q0) < Q1) {
            float4 v = ((const float4*)We)[j];
            uint32_t* d = t_We + 4 * j;
            d[0]=cvt_tf32(v.x); d[1]=cvt_tf32(v.y); d[2]=cvt_tf32(v.z); d[3]=cvt_tf32(v.w);
        } else if ((j -= Q1) < Q2) {
            float4 v = ((const float4*)W1)[j];
            uint32_t* d = t_W1 + 4 * j;
            d[0]=cvt_tf32(v.x); d[1]=cvt_tf32(v.y); d[2]=cvt_tf32(v.z); d[3]=cvt_tf32(v.w);
        } else if ((j -= Q2) < Q3) {
            float4 v = ((const float4*)W2)[j];
            uint32_t* d = t_W2 + 4 * j;
            d[0]=cvt_tf32(v.x); d[1]=cvt_tf32(v.y); d[2]=cvt_tf32(v.z); d[3]=cvt_tf32(v.w);
        } else {
            j -= Q3;
            float4 p = ((const float4*)attn_W)[2 * j];
            float4 q = ((const float4*)attn_W)[2 * j + 1];
            uint32_t* d = t_dW + 4 * j;
            d[0]=cvt_tf32(p.y - p.x); d[1]=cvt_tf32(p.w - p.z);
            d[2]=cvt_tf32(q.y - q.x); d[3]=cvt_tf32(q.w - q.z);
        }
    }
    if (tid0 < OBS) db[tid0] = attn_b[2 * tid0 + 1] - attn_b[2 * tid0];
}

// ---------------------------------------------------------------------------
// tf32 mma.sync GEMM, cp.async 3-stage pipeline + register-level fragment
// double buffering (B across ks, A across mt).
//   A:[M,K], B:[N,K] pre-converted tf32. C = act(A@B^T + bias).
//   Tile 128x128, BK=32, 256 thr (2x4 warps, 64x32 each), XOR-swizzled smem.
// ACT 0: tanh -> tf32 out. ACT 1: sigmoid -> fp32 C, C2 = tf32(obsp*sig).
// ---------------------------------------------------------------------------
template <int ACT>
__global__ __launch_bounds__(256, 2)
void mm_tf32p(const uint32_t* __restrict__ A, const uint32_t* __restrict__ B,
              const float* __restrict__ bias,
              void* __restrict__ Cv, uint32_t* __restrict__ C2,
              const float* __restrict__ obsp,
              int M, int N, int K) {
    extern __shared__ uint32_t sm[];   // 3 * 8192 words
    const int t    = threadIdx.x;
    const int lane = t & 31;
    const int wid  = t >> 5;
    const int wm   = wid & 1;
    const int wn   = wid >> 1;
    const int m0   = blockIdx.y * 128;
    const int n0   = blockIdx.x * 128;
    const int qr   = lane >> 2;
    const int qc   = lane & 3;

    const int r = t >> 3;
    const int q = t & 7;
    const uint32_t smB = smem_u32(sm);

    const uint32_t* aSrc[4];
    const uint32_t* bSrc[4];
    uint32_t aDst[4], bDst[4];
#pragma unroll
    for (int i = 0; i < 4; ++i) {
        int rr = r + (i << 5);
        aSrc[i] = A + (size_t)(m0 + rr) * K + (q << 2);
        bSrc[i] = B + (size_t)(n0 + rr) * K + (q << 2);
        uint32_t sw = (uint32_t)((q ^ (rr & 7)) << 2);
        aDst[i] = rr * 32 + sw;
        bDst[i] = 4096 + rr * 32 + sw;
    }

    const int NC = K >> 5;

#define ISSUE_CHUNK(c)                                                        \
    do {                                                                      \
        uint32_t so = (uint32_t)((c) % 3) * 8192u;                            \
        _Pragma("unroll")                                                     \
        for (int i = 0; i < 4; ++i) {                                         \
            uint32_t da = smB + ((so + aDst[i]) << 2);                        \
            asm volatile("cp.async.cg.shared.global [%0], [%1], 16;"          \
                         :: "r"(da), "l"(aSrc[i] + (c) * 32) : "memory");     \
        }                                                                     \
        _Pragma("unroll")                                                     \
        for (int i = 0; i < 4; ++i) {                                         \
            uint32_t dbp = smB + ((so + bDst[i]) << 2);                       \
            asm volatile("cp.async.cg.shared.global [%0], [%1], 16;"          \
                         :: "r"(dbp), "l"(bSrc[i] + (c) * 32) : "memory");    \
        }                                                                     \
        asm volatile("cp.async.commit_group;" ::: "memory");                  \
    } while (0)

// fragment loads (ks/mt compile-time under full unroll)
#define LDB(ks, buf)                                                          \
    do {                                                                      \
        const int ch_ = ((ks) << 1) ^ qr;                                     \
        _Pragma("unroll")                                                     \
        for (int nt = 0; nt < 4; ++nt) {                                      \
            uint32_t base_ = bB + (uint32_t)(wn * 32 + nt * 8 + qr) * 32 + qc;\
            bf[buf][nt][0] = sm[base_ + (ch_ << 2)];                          \
            bf[buf][nt][1] = sm[base_ + ((ch_ ^ 1) << 2)];                    \
        }                                                                     \
    } while (0)

#define LDA(ks, mt, buf)                                                      \
    do {                                                                      \
        const int ch_ = ((ks) << 1) ^ qr;                                     \
        const int rb_ = wm * 64 + (mt) * 16 + qr;                             \
        uint32_t ba0_ = bA + (uint32_t)rb_ * 32 + qc;                         \
        uint32_t ba1_ = ba0_ + 8 * 32;                                        \
        af[buf][0] = sm[ba0_ + (ch_ << 2)];                                   \
        af[buf][1] = sm[ba1_ + (ch_ << 2)];                                   \
        af[buf][2] = sm[ba0_ + ((ch_ ^ 1) << 2)];                             \
        af[buf][3] = sm[ba1_ + ((ch_ ^ 1) << 2)];                             \
    } while (0)

    float acc[4][4][4];
#pragma unroll
    for (int i = 0; i < 4; ++i)
#pragma unroll
        for (int j = 0; j < 4; ++j)
#pragma unroll
            for (int k = 0; k < 4; ++k) acc[i][j][k] = 0.0f;

    ISSUE_CHUNK(0);
    ISSUE_CHUNK(1);

    for (int c = 0; c < NC; ++c) {
        if (c + 1 < NC)
            asm volatile("cp.async.wait_group 1;" ::: "memory");
        else
            asm volatile("cp.async.wait_group 0;" ::: "memory");
        __syncthreads();

        const uint32_t bA = (uint32_t)(c % 3) * 8192u;
        const uint32_t bB = bA + 4096u;

        uint32_t bf[2][4][2];
        uint32_t af[2][4];

        LDB(0, 0);
        LDA(0, 0, 0);
        if (c + 2 < NC) ISSUE_CHUNK(c + 2);

#pragma unroll
        for (int ks = 0; ks < 4; ++ks) {
            if (ks < 3) LDB(ks + 1, (ks + 1) & 1);
#pragma unroll
            for (int mt = 0; mt < 4; ++mt) {
                // prefetch next A fragment under current MMAs
                if (mt < 3)      LDA(ks, mt + 1, (mt + 1) & 1);
                else if (ks < 3) LDA(ks + 1, 0, 0);
                const uint32_t* a = af[mt & 1];
#pragma unroll
                for (int nt = 0; nt < 4; ++nt) {
                    asm volatile(
                        "mma.sync.aligned.m16n8k8.row.col.f32.tf32.tf32.f32 "
                        "{%0,%1,%2,%3}, {%4,%5,%6,%7}, {%8,%9}, {%0,%1,%2,%3};"
                        : "+f"(acc[mt][nt][0]), "+f"(acc[mt][nt][1]),
                          "+f"(acc[mt][nt][2]), "+f"(acc[mt][nt][3])
                        : "r"(a[0]), "r"(a[1]), "r"(a[2]), "r"(a[3]),
                          "r"(bf[ks & 1][nt][0]), "r"(bf[ks & 1][nt][1]));
                }
            }
        }
    }
#undef ISSUE_CHUNK
#undef LDB
#undef LDA

    // epilogue (MUFU tanh; sigmoid via tanh identity)
#pragma unroll
    for (int mt = 0; mt < 4; ++mt) {
        const int m = m0 + wm * 64 + mt * 16 + qr;
#pragma unroll
        for (int nt = 0; nt < 4; ++nt) {
            const int n = n0 + wn * 32 + nt * 8 + 2 * qc;
            const float bx = bias[n], by = bias[n + 1];
#pragma unroll
            for (int h = 0; h < 2; ++h) {
                const int mm = m + 8 * h;
                float vx = acc[mt][nt][2 * h + 0] + bx;
                float vy = acc[mt][nt][2 * h + 1] + by;
                if (ACT == 0) {
                    vx = tanh_ap(vx); vy = tanh_ap(vy);
                    uint2 o = make_uint2(cvt_tf32(vx), cvt_tf32(vy));
                    *(uint2*)((uint32_t*)Cv + (size_t)mm * N + n) = o;
                } else {
                    vx = sigmoid_ap(vx); vy = sigmoid_ap(vy);
                    *(float2*)((float*)Cv + (size_t)mm * N + n) = make_float2(vx, vy);
                    float2 ob = *(const float2*)(obsp + (size_t)mm * N + n);
                    uint2 s = make_uint2(cvt_tf32(ob.x * vx), cvt_tf32(ob.y * vy));
                    *(uint2*)(C2 + (size_t)mm * N + n) = s;
                }
            }
        }
    }
}

// ---------------------------------------------------------------------------
// GEMV: v[b] = dot(h2[b,:], W3) + b3
// ---------------------------------------------------------------------------
__global__ __launch_bounds__(256)
void gemv_kernel(const float* __restrict__ H, const float* __restrict__ W3,
                 const float* __restrict__ b3, float* __restrict__ out) {
    __shared__ float red[8];
    int b = blockIdx.x;
    const float* row = H + (size_t)b * H2D;
    float s = 0.0f;
    for (int k = threadIdx.x; k < H2D; k += 256)
        s = fmaf(row[k], W3[k], s);
    for (int off = 16; off > 0; off >>= 1)
        s += __shfl_down_sync(0xffffffffu, s, off);
    if ((threadIdx.x & 31) == 0) red[threadIdx.x >> 5] = s;
    __syncthreads();
    if (threadIdx.x == 0) {
        float tot = 0.0f;
#pragma unroll
        for (int w = 0; w < 8; w++) tot += red[w];
        out[b] = tot + b3[0];
    }
}

// ---------------------------------------------------------------------------
// Launch
// ---------------------------------------------------------------------------
extern "C" void kernel_launch(void* const* d_in, const int* in_sizes, int n_in,
                              void* d_out, int out_size) {
    const float* obs    = (const float*)d_in[0];
    const float* We     = (const float*)d_in[1];
    const float* be     = (const float*)d_in[2];
    const float* attn_W = (const float*)d_in[3];
    const float* attn_b = (const float*)d_in[4];
    const float* W1     = (const float*)d_in[5];
    const float* b1     = (const float*)d_in[6];
    const float* W2     = (const float*)d_in[7];
    const float* b2     = (const float*)d_in[8];
    const float* W3     = (const float*)d_in[9];
    const float* b3     = (const float*)d_in[10];

    float* out_v    = (float*)d_out;
    float* out_attn = (float*)d_out + Bsz;

    uint32_t *pobs, *pWe, *pdW, *pW1, *pW2, *pe, *psa, *ph1, *ph2;
    float* pdb;
    cudaGetSymbolAddress((void**)&pobs, t_obs);
    cudaGetSymbolAddress((void**)&pWe,  t_We);
    cudaGetSymbolAddress((void**)&pdW,  t_dW);
    cudaGetSymbolAddress((void**)&pW1,  t_W1);
    cudaGetSymbolAddress((void**)&pW2,  t_W2);
    cudaGetSymbolAddress((void**)&pe,   t_e);
    cudaGetSymbolAddress((void**)&psa,  t_sa);
    cudaGetSymbolAddress((void**)&ph1,  t_h1);
    cudaGetSymbolAddress((void**)&ph2,  t_h2);
    cudaGetSymbolAddress((void**)&pdb,  g_db);

    const int SMEM = 3 * 8192 * 4;   // 96 KB
    cudaFuncSetAttribute(mm_tf32p<0>, cudaFuncAttributeMaxDynamicSharedMemorySize, SMEM);
    cudaFuncSetAttribute(mm_tf32p<1>, cudaFuncAttributeMaxDynamicSharedMemorySize, SMEM);

    // 1) convert weights/inputs to tf32; fold softmax
    prep_all<<<2048, 256>>>(obs, We, W1, W2, attn_W, attn_b, pdb);

    // 2) e = tanh(obs @ We^T + be)  -> tf32        [4096,512]  K=1024
    mm_tf32p<0><<<dim3(EOUT / 128, Bsz / 128), 256, SMEM>>>(
        pobs, pWe, be, pe, nullptr, nullptr, Bsz, EOUT, OBS);

    // 3) att = sigmoid(e @ dW^T + db) -> fp32 out; sa = tf32(obs*att)
    mm_tf32p<1><<<dim3(OBS / 128, Bsz / 128), 256, SMEM>>>(
        pe, pdW, pdb, out_attn, psa, obs, Bsz, OBS, EOUT);

    // 4) h1 = tanh(sa @ W1^T + b1) -> tf32         [4096,2048] K=1024
    mm_tf32p<0><<<dim3(H1D / 128, Bsz / 128), 256, SMEM>>>(
        psa, pW1, b1, ph1, nullptr, nullptr, Bsz, H1D, OBS);

    // 5) h2 = tanh(h1 @ W2^T + b2) -> tf32         [4096,2048] K=2048
    mm_tf32p<0><<<dim3(H2D / 128, Bsz / 128), 256, SMEM>>>(
        ph1, pW2, b2, ph2, nullptr, nullptr, Bsz, H2D, H1D);

    // 6) v = h2 @ W3^T + b3                        [4096]
    gemv_kernel<<<Bsz, 256>>>((const float*)ph2, W3, b3, out_v);
}

// round 7
// speedup vs baseline: 9.1083x; 1.7496x over previous
#include <cuda_runtime.h>
#include <cuda_fp16.h>
#include <math.h>
#include <stdint.h>

#define Bsz   4096
#define OBS   1024
#define EOUT  512
#define H1D   2048
#define H2D   2048

// fp16 scratch stored as uint32 half2 words
__device__ uint32_t t_obs[Bsz * OBS / 2];
__device__ uint32_t t_We [EOUT * OBS / 2];
__device__ uint32_t t_dW [OBS * EOUT / 2];
__device__ uint32_t t_W1 [H1D * OBS / 2];
__device__ uint32_t t_W2 [H2D * H1D / 2];
__device__ uint32_t t_e  [Bsz * EOUT / 2];
__device__ uint32_t t_sa [Bsz * OBS / 2];
__device__ uint32_t t_h1 [Bsz * H1D / 2];
__device__ uint32_t t_h2 [Bsz * H2D / 2];
__device__ float    g_db [OBS];

__device__ __forceinline__ uint32_t pack_h2(float x, float y) {
    __half2 h = __floats2half2_rn(x, y);
    return *(uint32_t*)&h;
}
__device__ __forceinline__ float tanh_ap(float x) {
    float y;
    asm("tanh.approx.f32 %0, %1;" : "=f"(y) : "f"(x));
    return y;
}
__device__ __forceinline__ float sigmoid_ap(float x) {
    return 0.5f + 0.5f * tanh_ap(0.5f * x);
}
__device__ __forceinline__ uint32_t smem_u32(const void* p) {
    uint32_t a;
    asm("{ .reg .u64 t; cvta.to.shared.u64 t, %1; cvt.u32.u64 %0, t; }"
        : "=r"(a) : "l"(p));
    return a;
}

// ---------------------------------------------------------------------------
// prep: convert obs/We/W1/W2 to fp16; fold softmax -> sigmoid diff (fp16 dW)
// ---------------------------------------------------------------------------
__global__ void prep_all(const float* __restrict__ obs, const float* __restrict__ We,
                         const float* __restrict__ W1,  const float* __restrict__ W2,
                         const float* __restrict__ attn_W, const float* __restrict__ attn_b,
                         float* __restrict__ db) {
    const int Q0 = (Bsz * OBS) / 4, Q1 = (EOUT * OBS) / 4, Q2 = (H1D * OBS) / 4,
              Q3 = (H2D * H1D) / 4, Q4 = (OBS * EOUT) / 4;
    const int total = Q0 + Q1 + Q2 + Q3 + Q4;
    int tid0 = blockIdx.x * blockDim.x + threadIdx.x;
    for (int i = tid0; i < total; i += gridDim.x * blockDim.x) {
        int j = i;
        if (j < Q0) {
            float4 v = ((const float4*)obs)[j];
            t_obs[2*j]   = pack_h2(v.x, v.y);
            t_obs[2*j+1] = pack_h2(v.z, v.w);
        } else if ((j -= Q0) < Q1) {
            float4 v = ((const float4*)We)[j];
            t_We[2*j]   = pack_h2(v.x, v.y);
            t_We[2*j+1] = pack_h2(v.z, v.w);
        } else if ((j -= Q1) < Q2) {
            float4 v = ((const float4*)W1)[j];
            t_W1[2*j]   = pack_h2(v.x, v.y);
            t_W1[2*j+1] = pack_h2(v.z, v.w);
        } else if ((j -= Q2) < Q3) {
            float4 v = ((const float4*)W2)[j];
            t_W2[2*j]   = pack_h2(v.x, v.y);
            t_W2[2*j+1] = pack_h2(v.z, v.w);
        } else {
            j -= Q3;
            float4 p = ((const float4*)attn_W)[2 * j];
            float4 q = ((const float4*)attn_W)[2 * j + 1];
            t_dW[2*j]   = pack_h2(p.y - p.x, p.w - p.z);
            t_dW[2*j+1] = pack_h2(q.y - q.x, q.w - q.z);
        }
    }
    if (tid0 < OBS) db[tid0] = attn_b[2 * tid0 + 1] - attn_b[2 * tid0];
}

// ---------------------------------------------------------------------------
// fp16 mma.sync GEMM (m16n8k16), cp.async 3-stage pipeline + register-level
// fragment double buffering. Same geometry as the tf32 version: BK=64 halves
// = 32 words/row, chunk swizzle c^(r&7), fragment chunk ch=(ks<<1)^qr.
//   A:[M,K], B:[N,K] fp16 (half2 words). C = act(A@B^T + bias).
//   Tile 128x128, 256 thr (2x4 warps, 64x32 each). 96KB dynamic smem.
// ACT 0: tanh -> fp16 out. ACT 1: sigmoid -> fp32 C, C2 = h2(obsp*sig).
// ---------------------------------------------------------------------------
template <int ACT>
__global__ __launch_bounds__(256, 2)
void mm_fp16(const uint32_t* __restrict__ A, const uint32_t* __restrict__ B,
             const float* __restrict__ bias,
             void* __restrict__ Cv, uint32_t* __restrict__ C2,
             const float* __restrict__ obsp,
             int M, int N, int K) {
    extern __shared__ uint32_t sm[];   // 3 * 8192 words (A 4096 + B 4096 each)
    const int t    = threadIdx.x;
    const int lane = t & 31;
    const int wid  = t >> 5;
    const int wm   = wid & 1;
    const int wn   = wid >> 1;
    const int m0   = blockIdx.y * 128;
    const int n0   = blockIdx.x * 128;
    const int qr   = lane >> 2;
    const int qc   = lane & 3;
    const int Kw   = K >> 1;           // words per row

    const int r = t >> 3;              // 0..31
    const int q = t & 7;               // chunk 0..7
    const uint32_t smB = smem_u32(sm);

    const uint32_t* aSrc[4];
    const uint32_t* bSrc[4];
    uint32_t aDst[4], bDst[4];
#pragma unroll
    for (int i = 0; i < 4; ++i) {
        int rr = r + (i << 5);
        aSrc[i] = A + (size_t)(m0 + rr) * Kw + (q << 2);
        bSrc[i] = B + (size_t)(n0 + rr) * Kw + (q << 2);
        uint32_t sw = (uint32_t)((q ^ (rr & 7)) << 2);
        aDst[i] = rr * 32 + sw;
        bDst[i] = 4096 + rr * 32 + sw;
    }

    const int NC = K >> 6;             // chunks of 64 halves (32 words)

#define ISSUE_CHUNK(c)                                                        \
    do {                                                                      \
        uint32_t so = (uint32_t)((c) % 3) * 8192u;                            \
        _Pragma("unroll")                                                     \
        for (int i = 0; i < 4; ++i) {                                         \
            uint32_t da = smB + ((so + aDst[i]) << 2);                        \
            asm volatile("cp.async.cg.shared.global [%0], [%1], 16;"          \
                         :: "r"(da), "l"(aSrc[i] + (c) * 32) : "memory");     \
        }                                                                     \
        _Pragma("unroll")                                                     \
        for (int i = 0; i < 4; ++i) {                                         \
            uint32_t dbp = smB + ((so + bDst[i]) << 2);                       \
            asm volatile("cp.async.cg.shared.global [%0], [%1], 16;"          \
                         :: "r"(dbp), "l"(bSrc[i] + (c) * 32) : "memory");    \
        }                                                                     \
        asm volatile("cp.async.commit_group;" ::: "memory");                  \
    } while (0)

// B fragment: reg0 = (n=qr, k=2qc..2qc+1) word qc; reg1 = word qc+4 (k+8)
#define LDB(ks, buf)                                                          \
    do {                                                                      \
        const int ch_ = ((ks) << 1) ^ qr;                                     \
        _Pragma("unroll")                                                     \
        for (int nt = 0; nt < 4; ++nt) {                                      \
            uint32_t base_ = bB + (uint32_t)(wn * 32 + nt * 8 + qr) * 32 + qc;\
            bf[buf][nt][0] = sm[base_ + (ch_ << 2)];                          \
            bf[buf][nt][1] = sm[base_ + ((ch_ ^ 1) << 2)];                    \
        }                                                                     \
    } while (0)

// A fragment: reg0=(qr,word qc) reg1=(qr+8,word qc) reg2/3 = +4 words (k+8)
#define LDA(ks, mt, buf)                                                      \
    do {                                                                      \
        const int ch_ = ((ks) << 1) ^ qr;                                     \
        const int rb_ = wm * 64 + (mt) * 16 + qr;                             \
        uint32_t ba0_ = bA + (uint32_t)rb_ * 32 + qc;                         \
        uint32_t ba1_ = ba0_ + 8 * 32;                                        \
        af[buf][0] = sm[ba0_ + (ch_ << 2)];                                   \
        af[buf][1] = sm[ba1_ + (ch_ << 2)];                                   \
        af[buf][2] = sm[ba0_ + ((ch_ ^ 1) << 2)];                             \
        af[buf][3] = sm[ba1_ + ((ch_ ^ 1) << 2)];                             \
    } while (0)

    float acc[4][4][4];
#pragma unroll
    for (int i = 0; i < 4; ++i)
#pragma unroll
        for (int j = 0; j < 4; ++j)
#pragma unroll
            for (int k = 0; k < 4; ++k) acc[i][j][k] = 0.0f;

    ISSUE_CHUNK(0);
    ISSUE_CHUNK(1);

    for (int c = 0; c < NC; ++c) {
        if (c + 1 < NC)
            asm volatile("cp.async.wait_group 1;" ::: "memory");
        else
            asm volatile("cp.async.wait_group 0;" ::: "memory");
        __syncthreads();

        const uint32_t bA = (uint32_t)(c % 3) * 8192u;
        const uint32_t bB = bA + 4096u;

        uint32_t bf[2][4][2];
        uint32_t af[2][4];

        LDB(0, 0);
        LDA(0, 0, 0);
        if (c + 2 < NC) ISSUE_CHUNK(c + 2);

#pragma unroll
        for (int ks = 0; ks < 4; ++ks) {       // 4 k-steps of 16
            if (ks < 3) LDB(ks + 1, (ks + 1) & 1);
#pragma unroll
            for (int mt = 0; mt < 4; ++mt) {
                if (mt < 3)      LDA(ks, mt + 1, (mt + 1) & 1);
                else if (ks < 3) LDA(ks + 1, 0, 0);
                const uint32_t* a = af[mt & 1];
#pragma unroll
                for (int nt = 0; nt < 4; ++nt) {
                    asm volatile(
                        "mma.sync.aligned.m16n8k16.row.col.f32.f16.f16.f32 "
                        "{%0,%1,%2,%3}, {%4,%5,%6,%7}, {%8,%9}, {%0,%1,%2,%3};"
                        : "+f"(acc[mt][nt][0]), "+f"(acc[mt][nt][1]),
                          "+f"(acc[mt][nt][2]), "+f"(acc[mt][nt][3])
                        : "r"(a[0]), "r"(a[1]), "r"(a[2]), "r"(a[3]),
                          "r"(bf[ks & 1][nt][0]), "r"(bf[ks & 1][nt][1]));
                }
            }
        }
    }
#undef ISSUE_CHUNK
#undef LDB
#undef LDA

    // epilogue: acc pair (c0,c1)=(m=qr, n=2qc,2qc+1), (c2,c3)=(m=qr+8, same)
    const int Nw = N >> 1;
#pragma unroll
    for (int mt = 0; mt < 4; ++mt) {
        const int m = m0 + wm * 64 + mt * 16 + qr;
#pragma unroll
        for (int nt = 0; nt < 4; ++nt) {
            const int n = n0 + wn * 32 + nt * 8 + 2 * qc;
            const float bx = bias[n], by = bias[n + 1];
#pragma unroll
            for (int h = 0; h < 2; ++h) {
                const int mm = m + 8 * h;
                float vx = acc[mt][nt][2 * h + 0] + bx;
                float vy = acc[mt][nt][2 * h + 1] + by;
                if (ACT == 0) {
                    vx = tanh_ap(vx); vy = tanh_ap(vy);
                    ((uint32_t*)Cv)[(size_t)mm * Nw + (n >> 1)] = pack_h2(vx, vy);
                } else {
                    vx = sigmoid_ap(vx); vy = sigmoid_ap(vy);
                    *(float2*)((float*)Cv + (size_t)mm * N + n) = make_float2(vx, vy);
                    float2 ob = *(const float2*)(obsp + (size_t)mm * N + n);
                    C2[(size_t)mm * Nw + (n >> 1)] = pack_h2(ob.x * vx, ob.y * vy);
                }
            }
        }
    }
}

// ---------------------------------------------------------------------------
// GEMV: v[b] = dot(h2[b,:], W3) + b3   (h2 fp16 half2 words)
// ---------------------------------------------------------------------------
__global__ __launch_bounds__(256)
void gemv_kernel(const uint32_t* __restrict__ H, const float* __restrict__ W3,
                 const float* __restrict__ b3, float* __restrict__ out) {
    __shared__ float red[8];
    int b = blockIdx.x;
    const uint32_t* row = H + (size_t)b * (H2D / 2);
    float s = 0.0f;
    for (int w = threadIdx.x; w < H2D / 2; w += 256) {
        __half2 hv = *(const __half2*)(row + w);
        float2 f = __half22float2(hv);
        s = fmaf(f.x, W3[2 * w], s);
        s = fmaf(f.y, W3[2 * w + 1], s);
    }
    for (int off = 16; off > 0; off >>= 1)
        s += __shfl_down_sync(0xffffffffu, s, off);
    if ((threadIdx.x & 31) == 0) red[threadIdx.x >> 5] = s;
    __syncthreads();
    if (threadIdx.x == 0) {
        float tot = 0.0f;
#pragma unroll
        for (int w = 0; w < 8; w++) tot += red[w];
        out[b] = tot + b3[0];
    }
}

// ---------------------------------------------------------------------------
// Launch
// ---------------------------------------------------------------------------
extern "C" void kernel_launch(void* const* d_in, const int* in_sizes, int n_in,
                              void* d_out, int out_size) {
    const float* obs    = (const float*)d_in[0];
    const float* We     = (const float*)d_in[1];
    const float* be     = (const float*)d_in[2];
    const float* attn_W = (const float*)d_in[3];
    const float* attn_b = (const float*)d_in[4];
    const float* W1     = (const float*)d_in[5];
    const float* b1     = (const float*)d_in[6];
    const float* W2     = (const float*)d_in[7];
    const float* b2     = (const float*)d_in[8];
    const float* W3     = (const float*)d_in[9];
    const float* b3     = (const float*)d_in[10];

    float* out_v    = (float*)d_out;
    float* out_attn = (float*)d_out + Bsz;

    uint32_t *pobs, *pWe, *pdW, *pW1, *pW2, *pe, *psa, *ph1, *ph2;
    float* pdb;
    cudaGetSymbolAddress((void**)&pobs, t_obs);
    cudaGetSymbolAddress((void**)&pWe,  t_We);
    cudaGetSymbolAddress((void**)&pdW,  t_dW);
    cudaGetSymbolAddress((void**)&pW1,  t_W1);
    cudaGetSymbolAddress((void**)&pW2,  t_W2);
    cudaGetSymbolAddress((void**)&pe,   t_e);
    cudaGetSymbolAddress((void**)&psa,  t_sa);
    cudaGetSymbolAddress((void**)&ph1,  t_h1);
    cudaGetSymbolAddress((void**)&ph2,  t_h2);
    cudaGetSymbolAddress((void**)&pdb,  g_db);

    const int SMEM = 3 * 8192 * 4;   // 96 KB
    cudaFuncSetAttribute(mm_fp16<0>, cudaFuncAttributeMaxDynamicSharedMemorySize, SMEM);
    cudaFuncSetAttribute(mm_fp16<1>, cudaFuncAttributeMaxDynamicSharedMemorySize, SMEM);

    // 1) convert weights/inputs to fp16; fold softmax
    prep_all<<<2048, 256>>>(obs, We, W1, W2, attn_W, attn_b, pdb);

    // 2) e = tanh(obs @ We^T + be)  -> fp16        [4096,512]  K=1024
    mm_fp16<0><<<dim3(EOUT / 128, Bsz / 128), 256, SMEM>>>(
        pobs, pWe, be, pe, nullptr, nullptr, Bsz, EOUT, OBS);

    // 3) att = sigmoid(e @ dW^T + db) -> fp32 out; sa = fp16(obs*att)
    mm_fp16<1><<<dim3(OBS / 128, Bsz / 128), 256, SMEM>>>(
        pe, pdW, pdb, out_attn, psa, obs, Bsz, OBS, EOUT);

    // 4) h1 = tanh(sa @ W1^T + b1) -> fp16         [4096,2048] K=1024
    mm_fp16<0><<<dim3(H1D / 128, Bsz / 128), 256, SMEM>>>(
        psa, pW1, b1, ph1, nullptr, nullptr, Bsz, H1D, OBS);

    // 5) h2 = tanh(h1 @ W2^T + b2) -> fp16         [4096,2048] K=2048
    mm_fp16<0><<<dim3(H2D / 128, Bsz / 128), 256, SMEM>>>(
        ph1, pW2, b2, ph2, nullptr, nullptr, Bsz, H2D, H1D);

    // 6) v = h2 @ W3^T + b3                        [4096]
    gemv_kernel<<<Bsz, 256>>>(ph2, W3, b3, out_v);
}

// round 8
// speedup vs baseline: 10.0995x; 1.1088x over previous
#include <cuda_runtime.h>
#include <cuda_fp16.h>
#include <math.h>
#include <stdint.h>

#define Bsz   4096
#define OBS   1024
#define EOUT  512
#define H1D   2048
#define H2D   2048

// fp16 scratch stored as uint32 half2 words
__device__ uint32_t t_obs[Bsz * OBS / 2];
__device__ uint32_t t_We [EOUT * OBS / 2];
__device__ uint32_t t_dW [OBS * EOUT / 2];
__device__ uint32_t t_W1 [H1D * OBS / 2];
__device__ uint32_t t_W2 [H2D * H1D / 2];
__device__ uint32_t t_e  [Bsz * EOUT / 2];
__device__ uint32_t t_sa [Bsz * OBS / 2];
__device__ uint32_t t_h1 [Bsz * H1D / 2];
__device__ uint32_t t_h2 [Bsz * H2D / 2];
__device__ float    g_db [OBS];

__device__ __forceinline__ uint32_t pack_h2(float x, float y) {
    __half2 h = __floats2half2_rn(x, y);
    return *(uint32_t*)&h;
}
__device__ __forceinline__ float tanh_ap(float x) {
    float y;
    asm("tanh.approx.f32 %0, %1;" : "=f"(y) : "f"(x));
    return y;
}
__device__ __forceinline__ float sigmoid_ap(float x) {
    return 0.5f + 0.5f * tanh_ap(0.5f * x);
}
__device__ __forceinline__ uint32_t smem_u32(const void* p) {
    uint32_t a;
    asm("{ .reg .u64 t; cvta.to.shared.u64 t, %1; cvt.u32.u64 %0, t; }"
        : "=r"(a) : "l"(p));
    return a;
}

// ---------------------------------------------------------------------------
// prep: convert obs/We/W1/W2 to fp16; fold softmax -> sigmoid diff (fp16 dW)
// ---------------------------------------------------------------------------
__global__ void prep_all(const float* __restrict__ obs, const float* __restrict__ We,
                         const float* __restrict__ W1,  const float* __restrict__ W2,
                         const float* __restrict__ attn_W, const float* __restrict__ attn_b,
                         float* __restrict__ db) {
    const int Q0 = (Bsz * OBS) / 4, Q1 = (EOUT * OBS) / 4, Q2 = (H1D * OBS) / 4,
              Q3 = (H2D * H1D) / 4, Q4 = (OBS * EOUT) / 4;
    const int total = Q0 + Q1 + Q2 + Q3 + Q4;
    int tid0 = blockIdx.x * blockDim.x + threadIdx.x;
    for (int i = tid0; i < total; i += gridDim.x * blockDim.x) {
        int j = i;
        if (j < Q0) {
            float4 v = ((const float4*)obs)[j];
            t_obs[2*j]   = pack_h2(v.x, v.y);
            t_obs[2*j+1] = pack_h2(v.z, v.w);
        } else if ((j -= Q0) < Q1) {
            float4 v = ((const float4*)We)[j];
            t_We[2*j]   = pack_h2(v.x, v.y);
            t_We[2*j+1] = pack_h2(v.z, v.w);
        } else if ((j -= Q1) < Q2) {
            float4 v = ((const float4*)W1)[j];
            t_W1[2*j]   = pack_h2(v.x, v.y);
            t_W1[2*j+1] = pack_h2(v.z, v.w);
        } else if ((j -= Q2) < Q3) {
            float4 v = ((const float4*)W2)[j];
            t_W2[2*j]   = pack_h2(v.x, v.y);
            t_W2[2*j+1] = pack_h2(v.z, v.w);
        } else {
            j -= Q3;
            float4 p = ((const float4*)attn_W)[2 * j];
            float4 q = ((const float4*)attn_W)[2 * j + 1];
            t_dW[2*j]   = pack_h2(p.y - p.x, p.w - p.z);
            t_dW[2*j+1] = pack_h2(q.y - q.x, q.w - q.z);
        }
    }
    if (tid0 < OBS) db[tid0] = attn_b[2 * tid0 + 1] - attn_b[2 * tid0];
}

// ---------------------------------------------------------------------------
// fp16 mma.sync GEMM (m16n8k16), cp.async 3-stage pipeline, ldmatrix.x4
// fragment loads, register-level fragment double buffering.
//   A:[M,K], B:[N,K] fp16 (half2 words). C = act(A@B^T + bias).
//   Tile 128x128, BK=64 halves (32 words/row), 256 thr (2x4 warps, 64x32).
//   Swizzle: 16B chunk c of row r stored at chunk c^(r&7).
// ACT 0: tanh -> fp16 out. ACT 1: sigmoid -> fp32 C, C2 = h2(obsp*sig).
// ---------------------------------------------------------------------------
template <int ACT>
__global__ __launch_bounds__(256, 2)
void mm_fp16(const uint32_t* __restrict__ A, const uint32_t* __restrict__ B,
             const float* __restrict__ bias,
             void* __restrict__ Cv, uint32_t* __restrict__ C2,
             const float* __restrict__ obsp,
             int M, int N, int K) {
    extern __shared__ uint32_t sm[];   // 3 * 8192 words (A 4096 + B 4096 each)
    const int t    = threadIdx.x;
    const int lane = t & 31;
    const int wid  = t >> 5;
    const int wm   = wid & 1;
    const int wn   = wid >> 1;
    const int m0   = blockIdx.y * 128;
    const int n0   = blockIdx.x * 128;
    const int qr   = lane >> 2;
    const int qc   = lane & 3;
    const int Kw   = K >> 1;           // words per row

    // ldmatrix per-lane geometry
    const int l7 = lane & 7;
    const int g  = lane >> 3;          // address group 0..3
    const int rowA = (g & 1) << 3;     // A: g0/g2 rows+0, g1/g3 rows+8
    const int chA  = g >> 1;           //    g0/g1 k-lo,   g2/g3 k-hi
    const int rowB = (g >> 1) << 3;    // B: g0/g1 rows+0, g2/g3 rows+8
    const int chB  = g & 1;            //    g0/g2 k-lo,   g1/g3 k-hi

    const int r = t >> 3;              // cp.async row 0..31
    const int q = t & 7;               // cp.async chunk 0..7
    const uint32_t smB = smem_u32(sm);

    const uint32_t* aSrc[4];
    const uint32_t* bSrc[4];
    uint32_t aDst[4], bDst[4];
#pragma unroll
    for (int i = 0; i < 4; ++i) {
        int rr = r + (i << 5);
        aSrc[i] = A + (size_t)(m0 + rr) * Kw + (q << 2);
        bSrc[i] = B + (size_t)(n0 + rr) * Kw + (q << 2);
        uint32_t sw = (uint32_t)((q ^ (rr & 7)) << 2);
        aDst[i] = rr * 32 + sw;
        bDst[i] = 4096 + rr * 32 + sw;
    }

    const int NC = K >> 6;             // chunks of 64 halves (32 words)

#define ISSUE_CHUNK(c)                                                        \
    do {                                                                      \
        uint32_t so = (uint32_t)((c) % 3) * 8192u;                            \
        _Pragma("unroll")                                                     \
        for (int i = 0; i < 4; ++i) {                                         \
            uint32_t da = smB + ((so + aDst[i]) << 2);                        \
            asm volatile("cp.async.cg.shared.global [%0], [%1], 16;"          \
                         :: "r"(da), "l"(aSrc[i] + (c) * 32) : "memory");     \
        }                                                                     \
        _Pragma("unroll")                                                     \
        for (int i = 0; i < 4; ++i) {                                         \
            uint32_t dbp = smB + ((so + bDst[i]) << 2);                       \
            asm volatile("cp.async.cg.shared.global [%0], [%1], 16;"          \
                         :: "r"(dbp), "l"(bSrc[i] + (c) * 32) : "memory");    \
        }                                                                     \
        asm volatile("cp.async.commit_group;" ::: "memory");                  \
    } while (0)

// A fragment via one ldmatrix.x4: r0..r3 = (m,klo),(m+8,klo),(m,khi),(m+8,khi)
#define LDA(ks, mt, buf)                                                      \
    do {                                                                      \
        uint32_t R_ = (uint32_t)(wm * 64 + (mt) * 16 + l7 + rowA);            \
        uint32_t C_ = (uint32_t)(((((ks) << 1) | chA) ^ l7) << 2);            \
        uint32_t ad_ = smB + ((bA + R_ * 32u + C_) << 2);                     \
        asm volatile("ldmatrix.sync.aligned.m8n8.x4.shared.b16 "              \
                     "{%0,%1,%2,%3}, [%4];"                                   \
                     : "=r"(af[buf][0]), "=r"(af[buf][1]),                    \
                       "=r"(af[buf][2]), "=r"(af[buf][3])                     \
                     : "r"(ad_));                                             \
    } while (0)

// B pair (nt=2p,2p+1) via one ldmatrix.x4: r0..r3 = (n,klo),(n,khi),(n+8,klo),(n+8,khi)
#define LDB1(ks, p, buf)                                                      \
    do {                                                                      \
        uint32_t R_ = (uint32_t)(wn * 32 + (p) * 16 + l7 + rowB);             \
        uint32_t C_ = (uint32_t)(((((ks) << 1) | chB) ^ l7) << 2);            \
        uint32_t ad_ = smB + ((bB + R_ * 32u + C_) << 2);                     \
        asm volatile("ldmatrix.sync.aligned.m8n8.x4.shared.b16 "              \
                     "{%0,%1,%2,%3}, [%4];"                                   \
                     : "=r"(bf[buf][2*(p)][0]),   "=r"(bf[buf][2*(p)][1]),    \
                       "=r"(bf[buf][2*(p)+1][0]), "=r"(bf[buf][2*(p)+1][1])   \
                     : "r"(ad_));                                             \
    } while (0)

#define LDB(ks, buf) do { LDB1(ks, 0, buf); LDB1(ks, 1, buf); } while (0)

    float acc[4][4][4];
#pragma unroll
    for (int i = 0; i < 4; ++i)
#pragma unroll
        for (int j = 0; j < 4; ++j)
#pragma unroll
            for (int k = 0; k < 4; ++k) acc[i][j][k] = 0.0f;

    ISSUE_CHUNK(0);
    ISSUE_CHUNK(1);

    for (int c = 0; c < NC; ++c) {
        if (c + 1 < NC)
            asm volatile("cp.async.wait_group 1;" ::: "memory");
        else
            asm volatile("cp.async.wait_group 0;" ::: "memory");
        __syncthreads();

        const uint32_t bA = (uint32_t)(c % 3) * 8192u;
        const uint32_t bB = bA + 4096u;

        uint32_t bf[2][4][2];
        uint32_t af[2][4];

        LDB(0, 0);
        LDA(0, 0, 0);
        if (c + 2 < NC) ISSUE_CHUNK(c + 2);

#pragma unroll
        for (int ks = 0; ks < 4; ++ks) {       // 4 k-steps of 16
            if (ks < 3) LDB(ks + 1, (ks + 1) & 1);
#pragma unroll
            for (int mt = 0; mt < 4; ++mt) {
                if (mt < 3)      LDA(ks, mt + 1, (mt + 1) & 1);
                else if (ks < 3) LDA(ks + 1, 0, 0);
                const uint32_t* a = af[mt & 1];
#pragma unroll
                for (int nt = 0; nt < 4; ++nt) {
                    asm volatile(
                        "mma.sync.aligned.m16n8k16.row.col.f32.f16.f16.f32 "
                        "{%0,%1,%2,%3}, {%4,%5,%6,%7}, {%8,%9}, {%0,%1,%2,%3};"
                        : "+f"(acc[mt][nt][0]), "+f"(acc[mt][nt][1]),
                          "+f"(acc[mt][nt][2]), "+f"(acc[mt][nt][3])
                        : "r"(a[0]), "r"(a[1]), "r"(a[2]), "r"(a[3]),
                          "r"(bf[ks & 1][nt][0]), "r"(bf[ks & 1][nt][1]));
                }
            }
        }
    }
#undef ISSUE_CHUNK
#undef LDA
#undef LDB1
#undef LDB

    // epilogue: acc pair (c0,c1)=(m=qr, n=2qc,2qc+1), (c2,c3)=(m=qr+8, same)
    const int Nw = N >> 1;
#pragma unroll
    for (int mt = 0; mt < 4; ++mt) {
        const int m = m0 + wm * 64 + mt * 16 + qr;
#pragma unroll
        for (int nt = 0; nt < 4; ++nt) {
            const int n = n0 + wn * 32 + nt * 8 + 2 * qc;
            const float bx = bias[n], by = bias[n + 1];
#pragma unroll
            for (int h = 0; h < 2; ++h) {
                const int mm = m + 8 * h;
                float vx = acc[mt][nt][2 * h + 0] + bx;
                float vy = acc[mt][nt][2 * h + 1] + by;
                if (ACT == 0) {
                    vx = tanh_ap(vx); vy = tanh_ap(vy);
                    ((uint32_t*)Cv)[(size_t)mm * Nw + (n >> 1)] = pack_h2(vx, vy);
                } else {
                    vx = sigmoid_ap(vx); vy = sigmoid_ap(vy);
                    *(float2*)((float*)Cv + (size_t)mm * N + n) = make_float2(vx, vy);
                    float2 ob = *(const float2*)(obsp + (size_t)mm * N + n);
                    C2[(size_t)mm * Nw + (n >> 1)] = pack_h2(ob.x * vx, ob.y * vy);
                }
            }
        }
    }
}

// ---------------------------------------------------------------------------
// GEMV: v[b] = dot(h2[b,:], W3) + b3   (h2 fp16 half2 words)
// ---------------------------------------------------------------------------
__global__ __launch_bounds__(256)
void gemv_kernel(const uint32_t* __restrict__ H, const float* __restrict__ W3,
                 const float* __restrict__ b3, float* __restrict__ out) {
    __shared__ float red[8];
    int b = blockIdx.x;
    const uint32_t* row = H + (size_t)b * (H2D / 2);
    float s = 0.0f;
    for (int w = threadIdx.x; w < H2D / 2; w += 256) {
        __half2 hv = *(const __half2*)(row + w);
        float2 f = __half22float2(hv);
        s = fmaf(f.x, W3[2 * w], s);
        s = fmaf(f.y, W3[2 * w + 1], s);
    }
    for (int off = 16; off > 0; off >>= 1)
        s += __shfl_down_sync(0xffffffffu, s, off);
    if ((threadIdx.x & 31) == 0) red[threadIdx.x >> 5] = s;
    __syncthreads();
    if (threadIdx.x == 0) {
        float tot = 0.0f;
#pragma unroll
        for (int w = 0; w < 8; w++) tot += red[w];
        out[b] = tot + b3[0];
    }
}

// ---------------------------------------------------------------------------
// Launch
// ---------------------------------------------------------------------------
extern "C" void kernel_launch(void* const* d_in, const int* in_sizes, int n_in,
                              void* d_out, int out_size) {
    const float* obs    = (const float*)d_in[0];
    const float* We     = (const float*)d_in[1];
    const float* be     = (const float*)d_in[2];
    const float* attn_W = (const float*)d_in[3];
    const float* attn_b = (const float*)d_in[4];
    const float* W1     = (const float*)d_in[5];
    const float* b1     = (const float*)d_in[6];
    const float* W2     = (const float*)d_in[7];
    const float* b2     = (const float*)d_in[8];
    const float* W3     = (const float*)d_in[9];
    const float* b3     = (const float*)d_in[10];

    float* out_v    = (float*)d_out;
    float* out_attn = (float*)d_out + Bsz;

    uint32_t *pobs, *pWe, *pdW, *pW1, *pW2, *pe, *psa, *ph1, *ph2;
    float* pdb;
    cudaGetSymbolAddress((void**)&pobs, t_obs);
    cudaGetSymbolAddress((void**)&pWe,  t_We);
    cudaGetSymbolAddress((void**)&pdW,  t_dW);
    cudaGetSymbolAddress((void**)&pW1,  t_W1);
    cudaGetSymbolAddress((void**)&pW2,  t_W2);
    cudaGetSymbolAddress((void**)&pe,   t_e);
    cudaGetSymbolAddress((void**)&psa,  t_sa);
    cudaGetSymbolAddress((void**)&ph1,  t_h1);
    cudaGetSymbolAddress((void**)&ph2,  t_h2);
    cudaGetSymbolAddress((void**)&pdb,  g_db);

    const int SMEM = 3 * 8192 * 4;   // 96 KB
    cudaFuncSetAttribute(mm_fp16<0>, cudaFuncAttributeMaxDynamicSharedMemorySize, SMEM);
    cudaFuncSetAttribute(mm_fp16<1>, cudaFuncAttributeMaxDynamicSharedMemorySize, SMEM);

    // 1) convert weights/inputs to fp16; fold softmax
    prep_all<<<2048, 256>>>(obs, We, W1, W2, attn_W, attn_b, pdb);

    // 2) e = tanh(obs @ We^T + be)  -> fp16        [4096,512]  K=1024
    mm_fp16<0><<<dim3(EOUT / 128, Bsz / 128), 256, SMEM>>>(
        pobs, pWe, be, pe, nullptr, nullptr, Bsz, EOUT, OBS);

    // 3) att = sigmoid(e @ dW^T + db) -> fp32 out; sa = fp16(obs*att)
    mm_fp16<1><<<dim3(OBS / 128, Bsz / 128), 256, SMEM>>>(
        pe, pdW, pdb, out_attn, psa, obs, Bsz, OBS, EOUT);

    // 4) h1 = tanh(sa @ W1^T + b1) -> fp16         [4096,2048] K=1024
    mm_fp16<0><<<dim3(H1D / 128, Bsz / 128), 256, SMEM>>>(
        psa, pW1, b1, ph1, nullptr, nullptr, Bsz, H1D, OBS);

    // 5) h2 = tanh(h1 @ W2^T + b2) -> fp16         [4096,2048] K=2048
    mm_fp16<0><<<dim3(H2D / 128, Bsz / 128), 256, SMEM>>>(
        ph1, pW2, b2, ph2, nullptr, nullptr, Bsz, H2D, H1D);

    // 6) v = h2 @ W3^T + b3                        [4096]
    gemv_kernel<<<Bsz, 256>>>(ph2, W3, b3, out_v);
}